// round 7
// baseline (speedup 1.0000x reference)
#include <cuda_runtime.h>
#include <cuda_fp16.h>
#include <cuda_fp8.h>
#include <stdint.h>

#define H_DIM 32
#define D_DIM 128
#define BM 128
#define BN 64
#define ROWP 136
#define SM_SCALE 0.08838834764831845f
#define LOG2E 1.4426950408889634f
#define SHIFT 14.0f
#define MAXTOT (4096*32*128)
#define MAXTOK (4096*32)

__device__ __align__(16) __half g_qh[MAXTOT];
__device__ __align__(16) __half g_kh[MAXTOT];
__device__ __align__(16) __half g_vh[MAXTOT];
__device__ float    g_qn[MAXTOK];
__device__ unsigned g_kmax[128];
__device__ unsigned g_absmax[3];

__device__ __forceinline__ unsigned sptr(const void* p) {
    return (unsigned)__cvta_generic_to_shared(p);
}
__device__ __forceinline__ float ex2(float x) {
    float y; asm("ex2.approx.ftz.f32 %0,%1;" : "=f"(y) : "f"(x)); return y;
}
__device__ __forceinline__ void cpa16(unsigned s, const void* g) {
    asm volatile("cp.async.cg.shared.global [%0],[%1],16;" :: "r"(s), "l"(g));
}
__device__ __forceinline__ void ldsm4(uint32_t& r0, uint32_t& r1, uint32_t& r2, uint32_t& r3, unsigned a) {
    asm volatile("ldmatrix.sync.aligned.m8n8.x4.shared.b16 {%0,%1,%2,%3},[%4];"
                 : "=r"(r0), "=r"(r1), "=r"(r2), "=r"(r3) : "r"(a));
}
__device__ __forceinline__ void ldsm4t(uint32_t& r0, uint32_t& r1, uint32_t& r2, uint32_t& r3, unsigned a) {
    asm volatile("ldmatrix.sync.aligned.m8n8.x4.trans.shared.b16 {%0,%1,%2,%3},[%4];"
                 : "=r"(r0), "=r"(r1), "=r"(r2), "=r"(r3) : "r"(a));
}
__device__ __forceinline__ void mma16816(float* c, const uint32_t* a, const uint32_t* b) {
    asm volatile("mma.sync.aligned.m16n8k16.row.col.f32.f16.f16.f32 "
                 "{%0,%1,%2,%3},{%4,%5,%6,%7},{%8,%9},{%0,%1,%2,%3};"
                 : "+f"(c[0]), "+f"(c[1]), "+f"(c[2]), "+f"(c[3])
                 : "r"(a[0]), "r"(a[1]), "r"(a[2]), "r"(a[3]), "r"(b[0]), "r"(b[1]));
}

__global__ void zero_kernel() {
    if (threadIdx.x < 3) g_absmax[threadIdx.x] = 0u;
    if (threadIdx.x < 128) g_kmax[threadIdx.x] = 0u;
}

__global__ void absmax_kernel(const float* __restrict__ q, const float* __restrict__ k,
                              const float* __restrict__ v, int n) {
    const float* p = blockIdx.y == 0 ? q : (blockIdx.y == 1 ? k : v);
    int n4 = n >> 2;
    float m = 0.f;
    for (int i = blockIdx.x * blockDim.x + threadIdx.x; i < n4; i += gridDim.x * blockDim.x) {
        float4 x = ((const float4*)p)[i];
        m = fmaxf(m, fmaxf(fmaxf(fabsf(x.x), fabsf(x.y)), fmaxf(fabsf(x.z), fabsf(x.w))));
    }
    #pragma unroll
    for (int o = 16; o; o >>= 1) m = fmaxf(m, __shfl_xor_sync(0xffffffffu, m, o));
    if ((threadIdx.x & 31) == 0) atomicMax(&g_absmax[blockIdx.y], __float_as_uint(m));
}

__device__ __forceinline__ __half qd(float x, float inv) {
    __nv_fp8_storage_t f8 = __nv_cvt_float_to_fp8(x * inv, __NV_SATFINITE, __NV_E4M3);
    __half_raw hr = __nv_cvt_fp8_to_halfraw(f8, __NV_E4M3);
    return *reinterpret_cast<__half*>(&hr);
}

// quantize + transpose [tok,H,D] -> [(b*H+h),S,D] fp16; also emit Q row norms and per-bh max K norm
__global__ void quant_kernel(const float* __restrict__ q, const float* __restrict__ k,
                             const float* __restrict__ v, int total, int S) {
    int t = blockIdx.y;
    const float* src = t == 0 ? q : (t == 1 ? k : v);
    __half* dst = t == 0 ? g_qh : (t == 1 ? g_kh : g_vh);
    float inv = 448.0f / __uint_as_float(g_absmax[t]);
    size_t i = (size_t)blockIdx.x * blockDim.x + threadIdx.x;
    size_t n4 = ((size_t)total << 12) >> 2;
    if (i >= n4) return;
    float4 x = ((const float4*)src)[i];
    size_t e0 = i << 2;
    int token = (int)(e0 >> 12);
    int rem = (int)(e0 & 4095);
    int hh = rem >> 7;
    int d = rem & 127;
    int bb = token / S;
    int s = token - bb * S;
    int bh = bb * H_DIM + hh;
    size_t o = (((size_t)bh * S + s) << 7) + d;
    __half rr[4];
    rr[0] = qd(x.x, inv); rr[1] = qd(x.y, inv);
    rr[2] = qd(x.z, inv); rr[3] = qd(x.w, inv);
    *(uint2*)(dst + o) = *(uint2*)rr;
    if (t < 2) {
        // each warp covers exactly one (token,h) row: 32 thr * 4 elems = 128
        float f0 = __half2float(rr[0]), f1 = __half2float(rr[1]);
        float f2 = __half2float(rr[2]), f3 = __half2float(rr[3]);
        float ss = f0 * f0 + f1 * f1 + f2 * f2 + f3 * f3;
        #pragma unroll
        for (int oo = 16; oo; oo >>= 1) ss += __shfl_xor_sync(0xffffffffu, ss, oo);
        if ((threadIdx.x & 31) == 0) {
            float nr = sqrtf(ss);
            if (t == 0) g_qn[(size_t)bh * S + s] = nr;
            else atomicMax(&g_kmax[bh], __float_as_uint(nr));
        }
    }
}

__global__ __launch_bounds__(256, 1) void fa_kernel(float* __restrict__ out, int S) {
    extern __shared__ __half smdyn[];
    __half (*KS)[ROWP] = (__half(*)[ROWP])smdyn;                    // [2*BN][ROWP]
    __half (*VS)[ROWP] = (__half(*)[ROWP])(smdyn + 2 * BN * ROWP);  // [2*BN][ROWP]

    const int bh = blockIdx.y;
    const int b = bh >> 5;
    const int h = bh & 31;
    const int qtile = blockIdx.x;
    const int q0 = qtile * BM;

    const size_t bhoff = (size_t)bh * S * D_DIM;
    const __half* Qg = g_qh + bhoff + (size_t)q0 * D_DIM;
    const __half* Kg = g_kh + bhoff;
    const __half* Vg = g_vh + bhoff;

    const int tid = threadIdx.x;
    const int warp = tid >> 5;
    const int lane = tid & 31;
    const int l8 = lane & 7;
    const int g = lane >> 3;
    const int m0 = warp * 16;
    const float NEG_INF = __int_as_float(0xff800000);

    const float aq = __uint_as_float(g_absmax[0]) / 448.0f;
    const float ak = __uint_as_float(g_absmax[1]) / 448.0f;
    const float av = __uint_as_float(g_absmax[2]) / 448.0f;
    const float c1 = aq * ak * SM_SCALE * LOG2E;
    const float km = __uint_as_float(g_kmax[bh]);

    // per-thread fixed exponent offsets (Cauchy-Schwarz bound): arg <= SHIFT always
    const int row0g = q0 + m0 + (lane >> 2);
    const int row1g = row0g + 8;
    const float cadd0 = SHIFT - g_qn[(size_t)bh * S + row0g] * km * c1;
    const float cadd1 = SHIFT - g_qn[(size_t)bh * S + row1g] * km * c1;

    // ---- stage Q (128x128) in KS[0..127], pull into A fragments ----
    #pragma unroll
    for (int it = 0; it < 8; it++) {
        int idx = tid + it * 256;
        int r = idx >> 4;
        int c = (idx & 15) * 8;
        cpa16(sptr(&KS[r][c]), Qg + (size_t)r * D_DIM + c);
    }
    asm volatile("cp.async.commit_group;");
    asm volatile("cp.async.wait_group 0;");
    __syncthreads();
    uint32_t qf[8][4];
    #pragma unroll
    for (int kt = 0; kt < 8; kt++) {
        unsigned a = sptr(&KS[m0 + ((g & 1) << 3) + l8][kt * 16 + ((g & 2) << 2)]);
        ldsm4(qf[kt][0], qf[kt][1], qf[kt][2], qf[kt][3], a);
    }
    __syncthreads();

    const int ntiles = 2 * qtile + 2;

    // ---- prologue: prefetch tile 0 into stage 0 ----
    {
        #pragma unroll
        for (int it = 0; it < 4; it++) {
            int idx = tid + it * 256;
            int r = idx >> 4;
            int c = (idx & 15) * 8;
            cpa16(sptr(&KS[r][c]), Kg + (size_t)r * D_DIM + c);
            cpa16(sptr(&VS[r][c]), Vg + (size_t)r * D_DIM + c);
        }
        asm volatile("cp.async.commit_group;");
    }

    float oacc[16][4];
    #pragma unroll
    for (int n = 0; n < 16; n++)
        #pragma unroll
        for (int e = 0; e < 4; e++) oacc[n][e] = 0.f;
    float lrow0 = 0.f, lrow1 = 0.f;

    for (int j = 0; j < ntiles; j++) {
        const int cur = j & 1;
        if (j + 1 < ntiles) {
            const __half* Kj = Kg + (size_t)(j + 1) * BN * D_DIM;
            const __half* Vj = Vg + (size_t)(j + 1) * BN * D_DIM;
            const int nx = (cur ^ 1) * BN;
            #pragma unroll
            for (int it = 0; it < 4; it++) {
                int idx = tid + it * 256;
                int r = idx >> 4;
                int c = (idx & 15) * 8;
                cpa16(sptr(&KS[nx + r][c]), Kj + (size_t)r * D_DIM + c);
                cpa16(sptr(&VS[nx + r][c]), Vj + (size_t)r * D_DIM + c);
            }
            asm volatile("cp.async.commit_group;");
            asm volatile("cp.async.wait_group 1;");
        } else {
            asm volatile("cp.async.wait_group 0;");
        }
        __syncthreads();

        const int kbase = cur * BN;
        const bool fullSkip = (j * BN > q0 + m0 + 15);
        if (!fullSkip) {
            // ---- S = Q @ K^T ----
            float sacc[8][4];
            #pragma unroll
            for (int n8 = 0; n8 < 8; n8++)
                #pragma unroll
                for (int e = 0; e < 4; e++) sacc[n8][e] = 0.f;

            #pragma unroll
            for (int n8 = 0; n8 < 8; n8++) {
                uint32_t kb[8][2];
                #pragma unroll
                for (int qq = 0; qq < 4; qq++) {
                    unsigned a = sptr(&KS[kbase + (n8 << 3) + l8][qq * 32 + (g << 3)]);
                    ldsm4(kb[2 * qq][0], kb[2 * qq][1], kb[2 * qq + 1][0], kb[2 * qq + 1][1], a);
                }
                #pragma unroll
                for (int kt = 0; kt < 8; kt++) mma16816(sacc[n8], qf[kt], kb[kt]);
            }

            // ---- causal mask (only near-diagonal warp tiles) ----
            if (j * BN + BN - 1 > q0 + m0) {
                const int col0 = j * BN + ((lane & 3) << 1);
                #pragma unroll
                for (int n8 = 0; n8 < 8; n8++)
                    #pragma unroll
                    for (int e = 0; e < 4; e++) {
                        int col = col0 + (n8 << 3) + (e & 1);
                        int row = (e & 2) ? row1g : row0g;
                        if (col > row) sacc[n8][e] = NEG_INF;
                    }
            }

            // ---- fixed-bound softmax: p = 2^(s*c1 + cadd), no max, no rescale ----
            float ps0 = 0.f, ps1 = 0.f;
            uint32_t pf[4][4];
            #pragma unroll
            for (int n8 = 0; n8 < 8; n8++) {
                float p0 = ex2(fmaf(sacc[n8][0], c1, cadd0));
                float p1 = ex2(fmaf(sacc[n8][1], c1, cadd0));
                float p2 = ex2(fmaf(sacc[n8][2], c1, cadd1));
                float p3 = ex2(fmaf(sacc[n8][3], c1, cadd1));
                ps0 += p0 + p1;
                ps1 += p2 + p3;
                __half2 h01 = __floats2half2_rn(p0, p1);
                __half2 h23 = __floats2half2_rn(p2, p3);
                int kt = n8 >> 1;
                if (n8 & 1) {
                    pf[kt][2] = *reinterpret_cast<uint32_t*>(&h01);
                    pf[kt][3] = *reinterpret_cast<uint32_t*>(&h23);
                } else {
                    pf[kt][0] = *reinterpret_cast<uint32_t*>(&h01);
                    pf[kt][1] = *reinterpret_cast<uint32_t*>(&h23);
                }
            }
            lrow0 += ps0;
            lrow1 += ps1;

            // ---- O += P @ V ----
            #pragma unroll
            for (int kt = 0; kt < 4; kt++) {
                int k0 = kt << 4;
                #pragma unroll
                for (int e = 0; e < 8; e++) {
                    uint32_t r0, r1, r2, r3;
                    unsigned a = sptr(&VS[kbase + k0 + ((g & 1) << 3) + l8][(e << 4) + ((g & 2) << 2)]);
                    ldsm4t(r0, r1, r2, r3, a);
                    uint32_t vb0[2] = {r0, r1}, vb1[2] = {r2, r3};
                    mma16816(oacc[2 * e], pf[kt], vb0);
                    mma16816(oacc[2 * e + 1], pf[kt], vb1);
                }
            }
        }
        __syncthreads();
    }

    // ---- epilogue ----
    lrow0 += __shfl_xor_sync(0xffffffffu, lrow0, 1);
    lrow0 += __shfl_xor_sync(0xffffffffu, lrow0, 2);
    lrow1 += __shfl_xor_sync(0xffffffffu, lrow1, 1);
    lrow1 += __shfl_xor_sync(0xffffffffu, lrow1, 2);
    float i0 = av / lrow0;
    float i1 = av / lrow1;
    size_t base0 = ((size_t)(b * S + row0g) * H_DIM + h) * D_DIM;
    size_t base1 = base0 + (size_t)8 * H_DIM * D_DIM;
    #pragma unroll
    for (int n = 0; n < 16; n++) {
        int col = (n << 3) + ((lane & 3) << 1);
        float2 v0 = {oacc[n][0] * i0, oacc[n][1] * i0};
        float2 v1 = {oacc[n][2] * i1, oacc[n][3] * i1};
        *(float2*)(out + base0 + col) = v0;
        *(float2*)(out + base1 + col) = v1;
    }
}

extern "C" void kernel_launch(void* const* d_in, const int* in_sizes, int n_in,
                              void* d_out, int out_size) {
    const float* q = (const float*)d_in[0];
    const float* k = (const float*)d_in[1];
    const float* v = (const float*)d_in[2];
    int n = in_sizes[0];
    int B = in_sizes[3] - 1;
    int total = n / (H_DIM * D_DIM);
    int S = total / B;

    const int smem_bytes = 4 * BN * ROWP * (int)sizeof(__half);  // 69632
    cudaFuncSetAttribute(fa_kernel, cudaFuncAttributeMaxDynamicSharedMemorySize, smem_bytes);

    zero_kernel<<<1, 128>>>();
    absmax_kernel<<<dim3(296, 3), 256>>>(q, k, v, n);
    int n4 = n >> 2;
    quant_kernel<<<dim3((n4 + 255) / 256, 3), 256>>>(q, k, v, total, S);
    fa_kernel<<<dim3(S / BM, B * H_DIM), 256, smem_bytes>>>((float*)d_out, S);
}

// round 8
// speedup vs baseline: 1.0737x; 1.0737x over previous
#include <cuda_runtime.h>
#include <cuda_fp16.h>
#include <cuda_fp8.h>
#include <stdint.h>

#define H_DIM 32
#define D_DIM 128
#define BM 128
#define BN 64
#define SM_SCALE 0.08838834764831845f
#define LOG2E 1.4426950408889634f
#define SHIFT 14.0f
#define MAXTOT (4096*32*128)
#define MAXTOK (4096*32)

#define KPITCH 144
#define VPITCH 272
#define KSTG   (BN * KPITCH)
#define VSTG   (BN * VPITCH)
#define VBASE  (2 * KSTG)
#define SMEMSZ (VBASE + 2 * VSTG)      // 53248

__device__ __align__(16) uint8_t g_q8[MAXTOT];
__device__ __align__(16) uint8_t g_k8[MAXTOT];
__device__ __align__(16) __half  g_vh[MAXTOT];
__device__ float    g_qn[MAXTOK];
__device__ unsigned g_kmax[128];
__device__ unsigned g_absmax[3];

__device__ __forceinline__ unsigned sptr(const void* p) {
    return (unsigned)__cvta_generic_to_shared(p);
}
__device__ __forceinline__ float ex2(float x) {
    float y; asm("ex2.approx.ftz.f32 %0,%1;" : "=f"(y) : "f"(x)); return y;
}
__device__ __forceinline__ void cpa16(unsigned s, const void* g) {
    asm volatile("cp.async.cg.shared.global [%0],[%1],16;" :: "r"(s), "l"(g));
}
__device__ __forceinline__ void ldsm4(uint32_t& r0, uint32_t& r1, uint32_t& r2, uint32_t& r3, unsigned a) {
    asm volatile("ldmatrix.sync.aligned.m8n8.x4.shared.b16 {%0,%1,%2,%3},[%4];"
                 : "=r"(r0), "=r"(r1), "=r"(r2), "=r"(r3) : "r"(a));
}
__device__ __forceinline__ void ldsm4t(uint32_t& r0, uint32_t& r1, uint32_t& r2, uint32_t& r3, unsigned a) {
    asm volatile("ldmatrix.sync.aligned.m8n8.x4.trans.shared.b16 {%0,%1,%2,%3},[%4];"
                 : "=r"(r0), "=r"(r1), "=r"(r2), "=r"(r3) : "r"(a));
}
__device__ __forceinline__ void mma16816(float* c, const uint32_t* a, const uint32_t* b) {
    asm volatile("mma.sync.aligned.m16n8k16.row.col.f32.f16.f16.f32 "
                 "{%0,%1,%2,%3},{%4,%5,%6,%7},{%8,%9},{%0,%1,%2,%3};"
                 : "+f"(c[0]), "+f"(c[1]), "+f"(c[2]), "+f"(c[3])
                 : "r"(a[0]), "r"(a[1]), "r"(a[2]), "r"(a[3]), "r"(b[0]), "r"(b[1]));
}
__device__ __forceinline__ void mmafp8(float* c, const uint32_t* a, const uint32_t* b) {
    asm volatile("mma.sync.aligned.m16n8k32.row.col.f32.e4m3.e4m3.f32 "
                 "{%0,%1,%2,%3},{%4,%5,%6,%7},{%8,%9},{%0,%1,%2,%3};"
                 : "+f"(c[0]), "+f"(c[1]), "+f"(c[2]), "+f"(c[3])
                 : "r"(a[0]), "r"(a[1]), "r"(a[2]), "r"(a[3]), "r"(b[0]), "r"(b[1]));
}

__global__ void zero_kernel() {
    if (threadIdx.x < 3) g_absmax[threadIdx.x] = 0u;
    if (threadIdx.x < 128) g_kmax[threadIdx.x] = 0u;
}

__global__ void absmax_kernel(const float* __restrict__ q, const float* __restrict__ k,
                              const float* __restrict__ v, int n) {
    const float* p = blockIdx.y == 0 ? q : (blockIdx.y == 1 ? k : v);
    int n4 = n >> 2;
    float m = 0.f;
    for (int i = blockIdx.x * blockDim.x + threadIdx.x; i < n4; i += gridDim.x * blockDim.x) {
        float4 x = ((const float4*)p)[i];
        m = fmaxf(m, fmaxf(fmaxf(fabsf(x.x), fabsf(x.y)), fmaxf(fabsf(x.z), fabsf(x.w))));
    }
    #pragma unroll
    for (int o = 16; o; o >>= 1) m = fmaxf(m, __shfl_xor_sync(0xffffffffu, m, o));
    if ((threadIdx.x & 31) == 0) atomicMax(&g_absmax[blockIdx.y], __float_as_uint(m));
}

// streaming quantize + transpose [tok,H,D] -> [(b*H+h),S,D]; Q/K raw e4m3 bytes, V dequant half
__global__ void quant_kernel(const float* __restrict__ q, const float* __restrict__ k,
                             const float* __restrict__ v, int total, int S) {
    int t = blockIdx.y;
    const float* src = t == 0 ? q : (t == 1 ? k : v);
    float inv = 448.0f / __uint_as_float(g_absmax[t]);
    size_t i = (size_t)blockIdx.x * blockDim.x + threadIdx.x;
    size_t n4 = ((size_t)total << 12) >> 2;
    if (i >= n4) return;
    float4 x = ((const float4*)src)[i];
    size_t e0 = i << 2;
    int token = (int)(e0 >> 12);
    int rem = (int)(e0 & 4095);
    int hh = rem >> 7;
    int d = rem & 127;
    int bb = token / S;
    int s = token - bb * S;
    size_t o = ((size_t)((bb * H_DIM + hh) * S + s) << 7) + d;

    uint8_t f0 = __nv_cvt_float_to_fp8(x.x * inv, __NV_SATFINITE, __NV_E4M3);
    uint8_t f1 = __nv_cvt_float_to_fp8(x.y * inv, __NV_SATFINITE, __NV_E4M3);
    uint8_t f2 = __nv_cvt_float_to_fp8(x.z * inv, __NV_SATFINITE, __NV_E4M3);
    uint8_t f3 = __nv_cvt_float_to_fp8(x.w * inv, __NV_SATFINITE, __NV_E4M3);
    if (t == 2) {
        __half rr[4];
        __half_raw h0 = __nv_cvt_fp8_to_halfraw(f0, __NV_E4M3);
        __half_raw h1 = __nv_cvt_fp8_to_halfraw(f1, __NV_E4M3);
        __half_raw h2 = __nv_cvt_fp8_to_halfraw(f2, __NV_E4M3);
        __half_raw h3 = __nv_cvt_fp8_to_halfraw(f3, __NV_E4M3);
        rr[0] = *(__half*)&h0; rr[1] = *(__half*)&h1;
        rr[2] = *(__half*)&h2; rr[3] = *(__half*)&h3;
        *(uint2*)(g_vh + o) = *(uint2*)rr;
    } else {
        uint8_t* dst = t == 0 ? g_q8 : g_k8;
        *(uchar4*)(dst + o) = make_uchar4(f0, f1, f2, f3);
    }
}

// row norms from the 1-byte quantized data: one warp per row, block-aggregated kmax atomics
__global__ void norm_kernel(int S) {
    __shared__ float sred[8];
    const int t = blockIdx.y;
    const uint8_t* src = t == 0 ? g_q8 : g_k8;
    const int wid = threadIdx.x >> 5, lane = threadIdx.x & 31;
    const int row = blockIdx.x * 8 + wid;
    uchar4 bb = *(const uchar4*)(src + (size_t)row * 128 + lane * 4);
    __half_raw h0 = __nv_cvt_fp8_to_halfraw(bb.x, __NV_E4M3);
    __half_raw h1 = __nv_cvt_fp8_to_halfraw(bb.y, __NV_E4M3);
    __half_raw h2 = __nv_cvt_fp8_to_halfraw(bb.z, __NV_E4M3);
    __half_raw h3 = __nv_cvt_fp8_to_halfraw(bb.w, __NV_E4M3);
    float f0 = __half2float(*(__half*)&h0), f1 = __half2float(*(__half*)&h1);
    float f2 = __half2float(*(__half*)&h2), f3 = __half2float(*(__half*)&h3);
    float ss = f0 * f0 + f1 * f1 + f2 * f2 + f3 * f3;
    #pragma unroll
    for (int o = 16; o; o >>= 1) ss += __shfl_xor_sync(0xffffffffu, ss, o);
    float nr = sqrtf(ss);
    if (t == 0) {
        if (lane == 0) g_qn[row] = nr;
    } else {
        if (lane == 0) sred[wid] = nr;
        __syncthreads();
        if (threadIdx.x == 0) {
            float m = sred[0];
            #pragma unroll
            for (int w = 1; w < 8; w++) m = fmaxf(m, sred[w]);
            atomicMax(&g_kmax[row / S], __float_as_uint(m));   // 8 rows/block share bh
        }
    }
}

__global__ __launch_bounds__(256, 1) void fa_kernel(float* __restrict__ out, int S) {
    extern __shared__ __align__(16) uint8_t SB[];

    const int bh = blockIdx.y;
    const int b = bh >> 5;
    const int h = bh & 31;
    const int qtile = blockIdx.x;
    const int q0 = qtile * BM;

    const size_t bhoff = (size_t)bh * S * D_DIM;
    const uint8_t* Qg = g_q8 + bhoff + (size_t)q0 * D_DIM;
    const uint8_t* Kg = g_k8 + bhoff;
    const __half*  Vg = g_vh + bhoff;

    const int tid = threadIdx.x;
    const int warp = tid >> 5;
    const int lane = tid & 31;
    const int l8 = lane & 7;
    const int g = lane >> 3;
    const int m0 = warp * 16;
    const float NEG_INF = __int_as_float(0xff800000);

    const float aq = __uint_as_float(g_absmax[0]) / 448.0f;
    const float ak = __uint_as_float(g_absmax[1]) / 448.0f;
    const float av = __uint_as_float(g_absmax[2]) / 448.0f;
    const float c1 = aq * ak * SM_SCALE * LOG2E;
    const float km = __uint_as_float(g_kmax[bh]);

    // fixed exponent offsets (Cauchy-Schwarz bound): exp2 arg <= SHIFT always
    const int row0g = q0 + m0 + (lane >> 2);
    const int row1g = row0g + 8;
    const float cadd0 = SHIFT - g_qn[(size_t)bh * S + row0g] * km * c1;
    const float cadd1 = SHIFT - g_qn[(size_t)bh * S + row1g] * km * c1;

    // ---- stage Q (128 rows x 128B fp8), pull A fragments ----
    #pragma unroll
    for (int it = 0; it < 4; it++) {
        int idx = tid + it * 256;
        int r = idx >> 3;
        int c = (idx & 7) * 16;
        cpa16(sptr(SB + r * KPITCH + c), Qg + (size_t)r * D_DIM + c);
    }
    asm volatile("cp.async.commit_group;");
    asm volatile("cp.async.wait_group 0;");
    __syncthreads();
    uint32_t qf[4][4];
    {
        int row = m0 + ((g & 1) << 3) + l8;
        #pragma unroll
        for (int kt = 0; kt < 4; kt++) {
            unsigned a = sptr(SB + row * KPITCH + kt * 32 + ((g & 2) << 3));
            ldsm4(qf[kt][0], qf[kt][1], qf[kt][2], qf[kt][3], a);
        }
    }
    __syncthreads();

    const int ntiles = 2 * qtile + 2;

    // prologue: prefetch tile 0
    {
        #pragma unroll
        for (int it = 0; it < 2; it++) {
            int idx = tid + it * 256;
            int r = idx >> 3;
            int c = (idx & 7) * 16;
            cpa16(sptr(SB + r * KPITCH + c), Kg + (size_t)r * D_DIM + c);
        }
        #pragma unroll
        for (int it = 0; it < 4; it++) {
            int idx = tid + it * 256;
            int r = idx >> 4;
            int c = (idx & 15) * 16;
            cpa16(sptr(SB + VBASE + r * VPITCH + c), (const uint8_t*)Vg + (size_t)r * 256 + c);
        }
        asm volatile("cp.async.commit_group;");
    }

    float oacc[16][4];
    #pragma unroll
    for (int n = 0; n < 16; n++)
        #pragma unroll
        for (int e = 0; e < 4; e++) oacc[n][e] = 0.f;
    float lrow0 = 0.f, lrow1 = 0.f;

    for (int j = 0; j < ntiles; j++) {
        const int cur = j & 1;
        if (j + 1 < ntiles) {
            const uint8_t* Kj = Kg + (size_t)(j + 1) * BN * D_DIM;
            const uint8_t* Vj = (const uint8_t*)(Vg + (size_t)(j + 1) * BN * D_DIM);
            const int ks = (cur ^ 1) * KSTG;
            const int vs = VBASE + (cur ^ 1) * VSTG;
            #pragma unroll
            for (int it = 0; it < 2; it++) {
                int idx = tid + it * 256;
                int r = idx >> 3;
                int c = (idx & 7) * 16;
                cpa16(sptr(SB + ks + r * KPITCH + c), Kj + (size_t)r * D_DIM + c);
            }
            #pragma unroll
            for (int it = 0; it < 4; it++) {
                int idx = tid + it * 256;
                int r = idx >> 4;
                int c = (idx & 15) * 16;
                cpa16(sptr(SB + vs + r * VPITCH + c), Vj + (size_t)r * 256 + c);
            }
            asm volatile("cp.async.commit_group;");
            asm volatile("cp.async.wait_group 1;");
        } else {
            asm volatile("cp.async.wait_group 0;");
        }
        __syncthreads();

        const uint8_t* Ks = SB + cur * KSTG;
        const uint8_t* Vs = SB + VBASE + cur * VSTG;
        const bool fullSkip = (j * BN > q0 + m0 + 15);
        if (!fullSkip) {
            // ---- S = Q @ K^T (fp8 e4m3 MMA) ----
            float sacc[8][4];
            #pragma unroll
            for (int n8 = 0; n8 < 8; n8++)
                #pragma unroll
                for (int e = 0; e < 4; e++) sacc[n8][e] = 0.f;

            #pragma unroll
            for (int grp = 0; grp < 2; grp++) {
                uint32_t kb[4][4][2];
                #pragma unroll
                for (int n4 = 0; n4 < 4; n4++) {
                    int krow = ((grp * 4 + n4) << 3) + l8;
                    #pragma unroll
                    for (int qq = 0; qq < 2; qq++) {
                        unsigned a = sptr(Ks + krow * KPITCH + qq * 64 + (g << 4));
                        ldsm4(kb[n4][2 * qq][0], kb[n4][2 * qq][1],
                              kb[n4][2 * qq + 1][0], kb[n4][2 * qq + 1][1], a);
                    }
                }
                #pragma unroll
                for (int kt = 0; kt < 4; kt++)
                    #pragma unroll
                    for (int n4 = 0; n4 < 4; n4++)
                        mmafp8(sacc[grp * 4 + n4], qf[kt], kb[n4][kt]);
            }

            // ---- causal mask ----
            if (j * BN + BN - 1 > q0 + m0) {
                const int col0 = j * BN + ((lane & 3) << 1);
                #pragma unroll
                for (int n8 = 0; n8 < 8; n8++)
                    #pragma unroll
                    for (int e = 0; e < 4; e++) {
                        int col = col0 + (n8 << 3) + (e & 1);
                        int row = (e & 2) ? row1g : row0g;
                        if (col > row) sacc[n8][e] = NEG_INF;
                    }
            }

            // ---- fixed-bound softmax: no max, no rescale ----
            float ps0 = 0.f, ps1 = 0.f;
            uint32_t pf[4][4];
            #pragma unroll
            for (int n8 = 0; n8 < 8; n8++) {
                float p0 = ex2(fmaf(sacc[n8][0], c1, cadd0));
                float p1 = ex2(fmaf(sacc[n8][1], c1, cadd0));
                float p2 = ex2(fmaf(sacc[n8][2], c1, cadd1));
                float p3 = ex2(fmaf(sacc[n8][3], c1, cadd1));
                ps0 += p0 + p1;
                ps1 += p2 + p3;
                __half2 h01 = __floats2half2_rn(p0, p1);
                __half2 h23 = __floats2half2_rn(p2, p3);
                int kt = n8 >> 1;
                if (n8 & 1) {
                    pf[kt][2] = *reinterpret_cast<uint32_t*>(&h01);
                    pf[kt][3] = *reinterpret_cast<uint32_t*>(&h23);
                } else {
                    pf[kt][0] = *reinterpret_cast<uint32_t*>(&h01);
                    pf[kt][1] = *reinterpret_cast<uint32_t*>(&h23);
                }
            }
            lrow0 += ps0;
            lrow1 += ps1;

            // ---- O += P @ V (fp16) ----
            #pragma unroll
            for (int kt = 0; kt < 4; kt++) {
                int k0 = kt << 4;
                #pragma unroll
                for (int e = 0; e < 8; e++) {
                    uint32_t r0, r1, r2, r3;
                    unsigned a = sptr(Vs + (k0 + ((g & 1) << 3) + l8) * VPITCH
                                         + ((e << 4) + ((g & 2) << 2)) * 2);
                    ldsm4t(r0, r1, r2, r3, a);
                    uint32_t vb0[2] = {r0, r1}, vb1[2] = {r2, r3};
                    mma16816(oacc[2 * e], pf[kt], vb0);
                    mma16816(oacc[2 * e + 1], pf[kt], vb1);
                }
            }
        }
        __syncthreads();
    }

    // ---- epilogue ----
    lrow0 += __shfl_xor_sync(0xffffffffu, lrow0, 1);
    lrow0 += __shfl_xor_sync(0xffffffffu, lrow0, 2);
    lrow1 += __shfl_xor_sync(0xffffffffu, lrow1, 1);
    lrow1 += __shfl_xor_sync(0xffffffffu, lrow1, 2);
    float i0 = av / lrow0;
    float i1 = av / lrow1;
    size_t base0 = ((size_t)(b * S + row0g) * H_DIM + h) * D_DIM;
    size_t base1 = base0 + (size_t)8 * H_DIM * D_DIM;
    #pragma unroll
    for (int n = 0; n < 16; n++) {
        int col = (n << 3) + ((lane & 3) << 1);
        float2 v0 = {oacc[n][0] * i0, oacc[n][1] * i0};
        float2 v1 = {oacc[n][2] * i1, oacc[n][3] * i1};
        *(float2*)(out + base0 + col) = v0;
        *(float2*)(out + base1 + col) = v1;
    }
}

extern "C" void kernel_launch(void* const* d_in, const int* in_sizes, int n_in,
                              void* d_out, int out_size) {
    const float* q = (const float*)d_in[0];
    const float* k = (const float*)d_in[1];
    const float* v = (const float*)d_in[2];
    int n = in_sizes[0];
    int B = in_sizes[3] - 1;
    int total = n / (H_DIM * D_DIM);
    int S = total / B;
    int rows = total * H_DIM;

    cudaFuncSetAttribute(fa_kernel, cudaFuncAttributeMaxDynamicSharedMemorySize, SMEMSZ);

    zero_kernel<<<1, 128>>>();
    absmax_kernel<<<dim3(296, 3), 256>>>(q, k, v, n);
    int n4 = n >> 2;
    quant_kernel<<<dim3((n4 + 255) / 256, 3), 256>>>(q, k, v, total, S);
    norm_kernel<<<dim3(rows / 8, 2), 256>>>(S);
    fa_kernel<<<dim3(S / BM, B * H_DIM), 256, SMEMSZ>>>((float*)d_out, S);
}

// round 10
// speedup vs baseline: 1.1705x; 1.0901x over previous
#include <cuda_runtime.h>
#include <cuda_fp16.h>
#include <cuda_fp8.h>
#include <stdint.h>

#define H_DIM 32
#define D_DIM 128
#define BM 128
#define BN 64
#define ROWP 136
#define SM_SCALE 0.08838834764831845f
#define LOG2E 1.4426950408889634f
#define SHIFT 14.0f
#define MAXTOT (4096*32*128)

__device__ __align__(16) __half g_qh[MAXTOT];
__device__ __align__(16) __half g_kh[MAXTOT];
__device__ __align__(16) __half g_vh[MAXTOT];
__device__ unsigned g_absmax[3] = {0u, 0u, 0u};
__device__ unsigned g_kmax[128] = {};

__device__ __forceinline__ unsigned sptr(const void* p) {
    return (unsigned)__cvta_generic_to_shared(p);
}
__device__ __forceinline__ float ex2(float x) {
    float y; asm("ex2.approx.ftz.f32 %0,%1;" : "=f"(y) : "f"(x)); return y;
}
__device__ __forceinline__ void cpa16(unsigned s, const void* g) {
    asm volatile("cp.async.cg.shared.global [%0],[%1],16;" :: "r"(s), "l"(g));
}
__device__ __forceinline__ void ldsm4(uint32_t& r0, uint32_t& r1, uint32_t& r2, uint32_t& r3, unsigned a) {
    asm volatile("ldmatrix.sync.aligned.m8n8.x4.shared.b16 {%0,%1,%2,%3},[%4];"
                 : "=r"(r0), "=r"(r1), "=r"(r2), "=r"(r3) : "r"(a));
}
__device__ __forceinline__ void ldsm4t(uint32_t& r0, uint32_t& r1, uint32_t& r2, uint32_t& r3, unsigned a) {
    asm volatile("ldmatrix.sync.aligned.m8n8.x4.trans.shared.b16 {%0,%1,%2,%3},[%4];"
                 : "=r"(r0), "=r"(r1), "=r"(r2), "=r"(r3) : "r"(a));
}
__device__ __forceinline__ void mma16816(float* c, const uint32_t* a, const uint32_t* b) {
    asm volatile("mma.sync.aligned.m16n8k16.row.col.f32.f16.f16.f32 "
                 "{%0,%1,%2,%3},{%4,%5,%6,%7},{%8,%9},{%0,%1,%2,%3};"
                 : "+f"(c[0]), "+f"(c[1]), "+f"(c[2]), "+f"(c[3])
                 : "r"(a[0]), "r"(a[1]), "r"(a[2]), "r"(a[3]), "r"(b[0]), "r"(b[1]));
}

__global__ void absmax_kernel(const float* __restrict__ q, const float* __restrict__ k,
                              const float* __restrict__ v, int n) {
    const float* p = blockIdx.y == 0 ? q : (blockIdx.y == 1 ? k : v);
    int n4 = n >> 2;
    float m = 0.f;
    for (int i = blockIdx.x * blockDim.x + threadIdx.x; i < n4; i += gridDim.x * blockDim.x) {
        float4 x = ((const float4*)p)[i];
        m = fmaxf(m, fmaxf(fmaxf(fabsf(x.x), fabsf(x.y)), fmaxf(fabsf(x.z), fabsf(x.w))));
    }
    #pragma unroll
    for (int o = 16; o; o >>= 1) m = fmaxf(m, __shfl_xor_sync(0xffffffffu, m, o));
    if ((threadIdx.x & 31) == 0) atomicMax(&g_absmax[blockIdx.y], __float_as_uint(m));
}

__device__ __forceinline__ __half qd(float x, float inv) {
    __nv_fp8_storage_t f8 = __nv_cvt_float_to_fp8(x * inv, __NV_SATFINITE, __NV_E4M3);
    __half_raw hr = __nv_cvt_fp8_to_halfraw(f8, __NV_E4M3);
    return *reinterpret_cast<__half*>(&hr);
}

// pure streaming quantize + transpose [tok,H,D] -> [(b*H+h),S,D] fp16 (dequantized e4m3 values)
__global__ void quant_kernel(const float* __restrict__ q, const float* __restrict__ k,
                             const float* __restrict__ v, int total, int S) {
    int t = blockIdx.y;
    const float* src = t == 0 ? q : (t == 1 ? k : v);
    __half* dst = t == 0 ? g_qh : (t == 1 ? g_kh : g_vh);
    float inv = 448.0f / __uint_as_float(g_absmax[t]);
    size_t i = (size_t)blockIdx.x * blockDim.x + threadIdx.x;
    size_t n4 = ((size_t)total << 12) >> 2;
    if (i >= n4) return;
    float4 x = ((const float4*)src)[i];
    size_t e0 = i << 2;
    int token = (int)(e0 >> 12);
    int rem = (int)(e0 & 4095);
    int hh = rem >> 7;
    int d = rem & 127;
    int bb = token / S;
    int s = token - bb * S;
    size_t o = (((size_t)(bb * H_DIM + hh) * S + s) << 7) + d;
    __half rr[4];
    rr[0] = qd(x.x, inv); rr[1] = qd(x.y, inv);
    rr[2] = qd(x.z, inv); rr[3] = qd(x.w, inv);
    *(uint2*)(dst + o) = *(uint2*)rr;
}

// per-bh max K row norm from g_kh: 16 threads per row, uint4 loads, 1 atomic per block
__global__ void kmax_kernel(int S) {
    __shared__ float sm[16];
    const int tid = threadIdx.x;
    const int row = blockIdx.x * 16 + (tid >> 4);
    const int seg = (tid & 15) * 8;
    uint4 u = *(const uint4*)(g_kh + (size_t)row * D_DIM + seg);
    const __half2* hp = (const __half2*)&u;
    float ss = 0.f;
    #pragma unroll
    for (int i = 0; i < 4; i++) {
        float2 f = __half22float2(hp[i]);
        ss += f.x * f.x + f.y * f.y;
    }
    #pragma unroll
    for (int o = 1; o < 16; o <<= 1) ss += __shfl_xor_sync(0xffffffffu, ss, o);
    if ((tid & 15) == 0) sm[tid >> 4] = ss;
    __syncthreads();
    if (tid == 0) {
        float m = sm[0];
        #pragma unroll
        for (int i = 1; i < 16; i++) m = fmaxf(m, sm[i]);
        atomicMax(&g_kmax[row / S], __float_as_uint(sqrtf(m)));
    }
}

__global__ __launch_bounds__(256, 1) void fa_kernel(float* __restrict__ out, int S) {
    extern __shared__ __half smdyn[];
    __half (*KS)[ROWP] = (__half(*)[ROWP])smdyn;
    __half (*VS)[ROWP] = (__half(*)[ROWP])(smdyn + 2 * BN * ROWP);

    const int bh = blockIdx.y;
    const int b = bh >> 5;
    const int h = bh & 31;
    const int qtile = blockIdx.x;
    const int q0 = qtile * BM;

    const size_t bhoff = (size_t)bh * S * D_DIM;
    const __half* Qg = g_qh + bhoff + (size_t)q0 * D_DIM;
    const __half* Kg = g_kh + bhoff;
    const __half* Vg = g_vh + bhoff;

    const int tid = threadIdx.x;
    const int warp = tid >> 5;
    const int lane = tid & 31;
    const int l8 = lane & 7;
    const int g = lane >> 3;
    const int m0 = warp * 16;
    const float NEG_INF = __int_as_float(0xff800000);

    const float aq = __uint_as_float(g_absmax[0]) / 448.0f;
    const float ak = __uint_as_float(g_absmax[1]) / 448.0f;
    const float av = __uint_as_float(g_absmax[2]) / 448.0f;
    const float c1 = aq * ak * SM_SCALE * LOG2E;
    const float km = __uint_as_float(g_kmax[bh]);

    const int row0g = q0 + m0 + (lane >> 2);
    const int row1g = row0g + 8;

    // ---- stage Q (128x128) in KS[0..127], pull into A fragments ----
    #pragma unroll
    for (int it = 0; it < 8; it++) {
        int idx = tid + it * 256;
        int r = idx >> 4;
        int c = (idx & 15) * 8;
        cpa16(sptr(&KS[r][c]), Qg + (size_t)r * D_DIM + c);
    }
    asm volatile("cp.async.commit_group;");
    asm volatile("cp.async.wait_group 0;");
    __syncthreads();
    uint32_t qf[8][4];
    #pragma unroll
    for (int kt = 0; kt < 8; kt++) {
        unsigned a = sptr(&KS[m0 + ((g & 1) << 3) + l8][kt * 16 + ((g & 2) << 2)]);
        ldsm4(qf[kt][0], qf[kt][1], qf[kt][2], qf[kt][3], a);
    }
    __syncthreads();

    // ---- in-register Q row norms (regs {0,2}: row0, regs {1,3}: row1) ----
    float ss0 = 0.f, ss1 = 0.f;
    #pragma unroll
    for (int kt = 0; kt < 8; kt++) {
        float2 f0 = __half22float2(*(__half2*)&qf[kt][0]);
        float2 f1 = __half22float2(*(__half2*)&qf[kt][1]);
        float2 f2 = __half22float2(*(__half2*)&qf[kt][2]);
        float2 f3 = __half22float2(*(__half2*)&qf[kt][3]);
        ss0 += f0.x * f0.x + f0.y * f0.y + f2.x * f2.x + f2.y * f2.y;
        ss1 += f1.x * f1.x + f1.y * f1.y + f3.x * f3.x + f3.y * f3.y;
    }
    ss0 += __shfl_xor_sync(0xffffffffu, ss0, 1);
    ss0 += __shfl_xor_sync(0xffffffffu, ss0, 2);
    ss1 += __shfl_xor_sync(0xffffffffu, ss1, 1);
    ss1 += __shfl_xor_sync(0xffffffffu, ss1, 2);
    // fixed exponent offsets (Cauchy-Schwarz with measured kmax): exp2 arg <= SHIFT always
    const float cadd0 = SHIFT - sqrtf(ss0) * km * c1 * 1.0001f;
    const float cadd1 = SHIFT - sqrtf(ss1) * km * c1 * 1.0001f;

    const int ntiles = 2 * qtile + 2;

    // ---- prologue: prefetch tile 0 into stage 0 ----
    {
        #pragma unroll
        for (int it = 0; it < 4; it++) {
            int idx = tid + it * 256;
            int r = idx >> 4;
            int c = (idx & 15) * 8;
            cpa16(sptr(&KS[r][c]), Kg + (size_t)r * D_DIM + c);
            cpa16(sptr(&VS[r][c]), Vg + (size_t)r * D_DIM + c);
        }
        asm volatile("cp.async.commit_group;");
    }

    float oacc[16][4];
    #pragma unroll
    for (int n = 0; n < 16; n++)
        #pragma unroll
        for (int e = 0; e < 4; e++) oacc[n][e] = 0.f;
    float lrow0 = 0.f, lrow1 = 0.f;

    for (int j = 0; j < ntiles; j++) {
        const int cur = j & 1;
        if (j + 1 < ntiles) {
            const __half* Kj = Kg + (size_t)(j + 1) * BN * D_DIM;
            const __half* Vj = Vg + (size_t)(j + 1) * BN * D_DIM;
            const int nx = (cur ^ 1) * BN;
            #pragma unroll
            for (int it = 0; it < 4; it++) {
                int idx = tid + it * 256;
                int r = idx >> 4;
                int c = (idx & 15) * 8;
                cpa16(sptr(&KS[nx + r][c]), Kj + (size_t)r * D_DIM + c);
                cpa16(sptr(&VS[nx + r][c]), Vj + (size_t)r * D_DIM + c);
            }
            asm volatile("cp.async.commit_group;");
            asm volatile("cp.async.wait_group 1;");
        } else {
            asm volatile("cp.async.wait_group 0;");
        }
        __syncthreads();

        const int kbase = cur * BN;
        const bool fullSkip = (j * BN > q0 + m0 + 15);
        if (!fullSkip) {
            // ---- S = Q @ K^T ----
            float sacc[8][4];
            #pragma unroll
            for (int n8 = 0; n8 < 8; n8++)
                #pragma unroll
                for (int e = 0; e < 4; e++) sacc[n8][e] = 0.f;

            #pragma unroll
            for (int n8 = 0; n8 < 8; n8++) {
                uint32_t kb[8][2];
                #pragma unroll
                for (int qq = 0; qq < 4; qq++) {
                    unsigned a = sptr(&KS[kbase + (n8 << 3) + l8][qq * 32 + (g << 3)]);
                    ldsm4(kb[2 * qq][0], kb[2 * qq][1], kb[2 * qq + 1][0], kb[2 * qq + 1][1], a);
                }
                #pragma unroll
                for (int kt = 0; kt < 8; kt++) mma16816(sacc[n8], qf[kt], kb[kt]);
            }

            // ---- causal mask (only near-diagonal warp tiles) ----
            if (j * BN + BN - 1 > q0 + m0) {
                const int col0 = j * BN + ((lane & 3) << 1);
                #pragma unroll
                for (int n8 = 0; n8 < 8; n8++)
                    #pragma unroll
                    for (int e = 0; e < 4; e++) {
                        int col = col0 + (n8 << 3) + (e & 1);
                        int row = (e & 2) ? row1g : row0g;
                        if (col > row) sacc[n8][e] = NEG_INF;
                    }
            }

            // ---- fixed-bound softmax: no max, no rescale ----
            float ps0 = 0.f, ps1 = 0.f;
            uint32_t pf[4][4];
            #pragma unroll
            for (int n8 = 0; n8 < 8; n8++) {
                float p0 = ex2(fmaf(sacc[n8][0], c1, cadd0));
                float p1 = ex2(fmaf(sacc[n8][1], c1, cadd0));
                float p2 = ex2(fmaf(sacc[n8][2], c1, cadd1));
                float p3 = ex2(fmaf(sacc[n8][3], c1, cadd1));
                ps0 += p0 + p1;
                ps1 += p2 + p3;
                __half2 h01 = __floats2half2_rn(p0, p1);
                __half2 h23 = __floats2half2_rn(p2, p3);
                int kt = n8 >> 1;
                if (n8 & 1) {
                    pf[kt][2] = *reinterpret_cast<uint32_t*>(&h01);
                    pf[kt][3] = *reinterpret_cast<uint32_t*>(&h23);
                } else {
                    pf[kt][0] = *reinterpret_cast<uint32_t*>(&h01);
                    pf[kt][1] = *reinterpret_cast<uint32_t*>(&h23);
                }
            }
            lrow0 += ps0;
            lrow1 += ps1;

            // ---- O += P @ V ----
            #pragma unroll
            for (int kt = 0; kt < 4; kt++) {
                int k0 = kt << 4;
                #pragma unroll
                for (int e = 0; e < 8; e++) {
                    uint32_t r0, r1, r2, r3;
                    unsigned a = sptr(&VS[kbase + k0 + ((g & 1) << 3) + l8][(e << 4) + ((g & 2) << 2)]);
                    ldsm4t(r0, r1, r2, r3, a);
                    uint32_t vb0[2] = {r0, r1}, vb1[2] = {r2, r3};
                    mma16816(oacc[2 * e], pf[kt], vb0);
                    mma16816(oacc[2 * e + 1], pf[kt], vb1);
                }
            }
        }
        __syncthreads();
    }

    // ---- epilogue ----
    lrow0 += __shfl_xor_sync(0xffffffffu, lrow0, 1);
    lrow0 += __shfl_xor_sync(0xffffffffu, lrow0, 2);
    lrow1 += __shfl_xor_sync(0xffffffffu, lrow1, 1);
    lrow1 += __shfl_xor_sync(0xffffffffu, lrow1, 2);
    float i0 = av / lrow0;
    float i1 = av / lrow1;
    size_t base0 = ((size_t)(b * S + row0g) * H_DIM + h) * D_DIM;
    size_t base1 = base0 + (size_t)8 * H_DIM * D_DIM;
    #pragma unroll
    for (int n = 0; n < 16; n++) {
        int col = (n << 3) + ((lane & 3) << 1);
        float2 v0 = {oacc[n][0] * i0, oacc[n][1] * i0};
        float2 v1 = {oacc[n][2] * i1, oacc[n][3] * i1};
        *(float2*)(out + base0 + col) = v0;
        *(float2*)(out + base1 + col) = v1;
    }
}

extern "C" void kernel_launch(void* const* d_in, const int* in_sizes, int n_in,
                              void* d_out, int out_size) {
    const float* q = (const float*)d_in[0];
    const float* k = (const float*)d_in[1];
    const float* v = (const float*)d_in[2];
    int n = in_sizes[0];
    int B = in_sizes[3] - 1;
    int total = n / (H_DIM * D_DIM);
    int S = total / B;
    int rows = total * H_DIM;

    const int smem_bytes = 4 * BN * ROWP * (int)sizeof(__half);  // 69632
    cudaFuncSetAttribute(fa_kernel, cudaFuncAttributeMaxDynamicSharedMemorySize, smem_bytes);

    absmax_kernel<<<dim3(296, 3), 256>>>(q, k, v, n);
    int n4 = n >> 2;
    quant_kernel<<<dim3((n4 + 255) / 256, 3), 256>>>(q, k, v, total, S);
    kmax_kernel<<<rows / 16, 256>>>(S);
    fa_kernel<<<dim3(S / BM, B * H_DIM), 256, smem_bytes>>>((float*)d_out, S);
}

// round 11
// speedup vs baseline: 1.2742x; 1.0886x over previous
#include <cuda_runtime.h>
#include <cuda_fp16.h>
#include <cuda_fp8.h>
#include <stdint.h>

#define H_DIM 32
#define D_DIM 128
#define BM 128
#define BN 64
#define ROWP 136
#define SM_SCALE 0.08838834764831845f
#define LOG2E 1.4426950408889634f
#define SHIFT 14.0f
#define MAXTOT (4096*32*128)
// smem: KS[256][136] + VS[256][136] halves = 139264 B (4 stages of 64 rows each)
#define SMEMSZ (2 * 256 * ROWP * 2)

__device__ __align__(16) __half g_kh[MAXTOT];
__device__ __align__(16) __half g_vh[MAXTOT];
__device__ unsigned g_absmax[3] = {0u, 0u, 0u};
__device__ unsigned g_kmax[128] = {};

__device__ __forceinline__ unsigned sptr(const void* p) {
    return (unsigned)__cvta_generic_to_shared(p);
}
__device__ __forceinline__ float ex2(float x) {
    float y; asm("ex2.approx.ftz.f32 %0,%1;" : "=f"(y) : "f"(x)); return y;
}
__device__ __forceinline__ void cpa16(unsigned s, const void* g) {
    asm volatile("cp.async.cg.shared.global [%0],[%1],16;" :: "r"(s), "l"(g));
}
__device__ __forceinline__ void ldsm4(uint32_t& r0, uint32_t& r1, uint32_t& r2, uint32_t& r3, unsigned a) {
    asm volatile("ldmatrix.sync.aligned.m8n8.x4.shared.b16 {%0,%1,%2,%3},[%4];"
                 : "=r"(r0), "=r"(r1), "=r"(r2), "=r"(r3) : "r"(a));
}
__device__ __forceinline__ void ldsm4t(uint32_t& r0, uint32_t& r1, uint32_t& r2, uint32_t& r3, unsigned a) {
    asm volatile("ldmatrix.sync.aligned.m8n8.x4.trans.shared.b16 {%0,%1,%2,%3},[%4];"
                 : "=r"(r0), "=r"(r1), "=r"(r2), "=r"(r3) : "r"(a));
}
__device__ __forceinline__ void mma16816(float* c, const uint32_t* a, const uint32_t* b) {
    asm volatile("mma.sync.aligned.m16n8k16.row.col.f32.f16.f16.f32 "
                 "{%0,%1,%2,%3},{%4,%5,%6,%7},{%8,%9},{%0,%1,%2,%3};"
                 : "+f"(c[0]), "+f"(c[1]), "+f"(c[2]), "+f"(c[3])
                 : "r"(a[0]), "r"(a[1]), "r"(a[2]), "r"(a[3]), "r"(b[0]), "r"(b[1]));
}

__global__ void absmax_kernel(const float* __restrict__ q, const float* __restrict__ k,
                              const float* __restrict__ v, int n) {
    const float* p = blockIdx.y == 0 ? q : (blockIdx.y == 1 ? k : v);
    int n4 = n >> 2;
    float m = 0.f;
    for (int i = blockIdx.x * blockDim.x + threadIdx.x; i < n4; i += gridDim.x * blockDim.x) {
        float4 x = ((const float4*)p)[i];
        m = fmaxf(m, fmaxf(fmaxf(fabsf(x.x), fabsf(x.y)), fmaxf(fabsf(x.z), fabsf(x.w))));
    }
    #pragma unroll
    for (int o = 16; o; o >>= 1) m = fmaxf(m, __shfl_xor_sync(0xffffffffu, m, o));
    if ((threadIdx.x & 31) == 0) atomicMax(&g_absmax[blockIdx.y], __float_as_uint(m));
}

__device__ __forceinline__ __half qd(float x, float inv) {
    __nv_fp8_storage_t f8 = __nv_cvt_float_to_fp8(x * inv, __NV_SATFINITE, __NV_E4M3);
    __half_raw hr = __nv_cvt_fp8_to_halfraw(f8, __NV_E4M3);
    return *reinterpret_cast<__half*>(&hr);
}

// streaming quantize + transpose for K and V only (Q is fused into fa)
__global__ void quant_kernel(const float* __restrict__ k, const float* __restrict__ v,
                             int total, int S) {
    int t = blockIdx.y + 1;
    const float* src = t == 1 ? k : v;
    __half* dst = t == 1 ? g_kh : g_vh;
    float inv = 448.0f / __uint_as_float(g_absmax[t]);
    size_t i = (size_t)blockIdx.x * blockDim.x + threadIdx.x;
    size_t n4 = ((size_t)total << 12) >> 2;
    if (i >= n4) return;
    float4 x = ((const float4*)src)[i];
    size_t e0 = i << 2;
    int token = (int)(e0 >> 12);
    int rem = (int)(e0 & 4095);
    int hh = rem >> 7;
    int d = rem & 127;
    int bb = token / S;
    int s = token - bb * S;
    size_t o = (((size_t)(bb * H_DIM + hh) * S + s) << 7) + d;
    __half rr[4];
    rr[0] = qd(x.x, inv); rr[1] = qd(x.y, inv);
    rr[2] = qd(x.z, inv); rr[3] = qd(x.w, inv);
    *(uint2*)(dst + o) = *(uint2*)rr;
}

// per-bh max K row norm: 16 threads per row, uint4 loads, 1 atomic per block
__global__ void kmax_kernel(int S) {
    __shared__ float sm[16];
    const int tid = threadIdx.x;
    const int row = blockIdx.x * 16 + (tid >> 4);
    const int seg = (tid & 15) * 8;
    uint4 u = *(const uint4*)(g_kh + (size_t)row * D_DIM + seg);
    const __half2* hp = (const __half2*)&u;
    float ss = 0.f;
    #pragma unroll
    for (int i = 0; i < 4; i++) {
        float2 f = __half22float2(hp[i]);
        ss += f.x * f.x + f.y * f.y;
    }
    #pragma unroll
    for (int o = 1; o < 16; o <<= 1) ss += __shfl_xor_sync(0xffffffffu, ss, o);
    if ((tid & 15) == 0) sm[tid >> 4] = ss;
    __syncthreads();
    if (tid == 0) {
        float m = sm[0];
        #pragma unroll
        for (int i = 1; i < 16; i++) m = fmaxf(m, sm[i]);
        atomicMax(&g_kmax[row / S], __float_as_uint(sqrtf(m)));
    }
}

__global__ __launch_bounds__(256, 1) void fa_kernel(float* __restrict__ out,
                                                    const float* __restrict__ qsrc, int S) {
    extern __shared__ __half smdyn[];
    __half (*KS)[ROWP] = (__half(*)[ROWP])smdyn;                    // 4 stages x 64 rows
    __half (*VS)[ROWP] = (__half(*)[ROWP])(smdyn + 256 * ROWP);

    const int bh = blockIdx.y;
    const int b = bh >> 5;
    const int h = bh & 31;
    const int qtile = blockIdx.x;
    const int q0 = qtile * BM;

    const size_t bhoff = (size_t)bh * S * D_DIM;
    const __half* Kg = g_kh + bhoff;
    const __half* Vg = g_vh + bhoff;

    const int tid = threadIdx.x;
    const int warp = tid >> 5;
    const int lane = tid & 31;
    const int l8 = lane & 7;
    const int g = lane >> 3;
    const int m0 = warp * 16;
    const float NEG_INF = __int_as_float(0xff800000);

    const float aq = __uint_as_float(g_absmax[0]) / 448.0f;
    const float ak = __uint_as_float(g_absmax[1]) / 448.0f;
    const float av = __uint_as_float(g_absmax[2]) / 448.0f;
    const float c1 = aq * ak * SM_SCALE * LOG2E;
    const float km = __uint_as_float(g_kmax[bh]);

    const int row0g = q0 + m0 + (lane >> 2);
    const int row1g = row0g + 8;

    // ---- fused Q: load fp32, quantize e4m3, store unscaled fp16 into KS rows 0..127 ----
    {
        const float invq = 448.0f / __uint_as_float(g_absmax[0]);
        const float* Qf = qsrc + ((size_t)(b * S + q0) * H_DIM + h) * D_DIM;
        #pragma unroll
        for (int it = 0; it < 16; it++) {
            int idx = tid + it * 256;
            int r = idx >> 5;
            int c4 = (idx & 31) * 4;
            float4 x = *(const float4*)(Qf + (size_t)r * H_DIM * D_DIM + c4);
            __half rr[4];
            rr[0] = qd(x.x, invq); rr[1] = qd(x.y, invq);
            rr[2] = qd(x.z, invq); rr[3] = qd(x.w, invq);
            *(uint2*)&KS[r][c4] = *(uint2*)rr;
        }
    }
    __syncthreads();
    uint32_t qf[8][4];
    #pragma unroll
    for (int kt = 0; kt < 8; kt++) {
        unsigned a = sptr(&KS[m0 + ((g & 1) << 3) + l8][kt * 16 + ((g & 2) << 2)]);
        ldsm4(qf[kt][0], qf[kt][1], qf[kt][2], qf[kt][3], a);
    }
    __syncthreads();

    // ---- in-register Q row norms ----
    float ss0 = 0.f, ss1 = 0.f;
    #pragma unroll
    for (int kt = 0; kt < 8; kt++) {
        float2 f0 = __half22float2(*(__half2*)&qf[kt][0]);
        float2 f1 = __half22float2(*(__half2*)&qf[kt][1]);
        float2 f2 = __half22float2(*(__half2*)&qf[kt][2]);
        float2 f3 = __half22float2(*(__half2*)&qf[kt][3]);
        ss0 += f0.x * f0.x + f0.y * f0.y + f2.x * f2.x + f2.y * f2.y;
        ss1 += f1.x * f1.x + f1.y * f1.y + f3.x * f3.x + f3.y * f3.y;
    }
    ss0 += __shfl_xor_sync(0xffffffffu, ss0, 1);
    ss0 += __shfl_xor_sync(0xffffffffu, ss0, 2);
    ss1 += __shfl_xor_sync(0xffffffffu, ss1, 1);
    ss1 += __shfl_xor_sync(0xffffffffu, ss1, 2);
    const float cadd0 = SHIFT - sqrtf(ss0) * km * c1 * 1.0001f;
    const float cadd1 = SHIFT - sqrtf(ss1) * km * c1 * 1.0001f;

    const int ntiles = 2 * qtile + 2;   // always even

    // ---- prologue: prefetch pair 0 (tiles 0,1 = 128 rows) into stage-pair 0 ----
    {
        #pragma unroll
        for (int it = 0; it < 8; it++) {
            int idx = tid + it * 256;
            int r = idx >> 4;
            int c = (idx & 15) * 8;
            cpa16(sptr(&KS[r][c]), Kg + (size_t)r * D_DIM + c);
            cpa16(sptr(&VS[r][c]), Vg + (size_t)r * D_DIM + c);
        }
        asm volatile("cp.async.commit_group;");
    }

    float oacc[16][4];
    #pragma unroll
    for (int n = 0; n < 16; n++)
        #pragma unroll
        for (int e = 0; e < 4; e++) oacc[n][e] = 0.f;
    float lrow0 = 0.f, lrow1 = 0.f;

    for (int jj = 0; jj < ntiles; jj += 2) {
        const int stage = (jj >> 1) & 1;
        if (jj + 2 < ntiles) {
            const __half* Kj = Kg + (size_t)(jj + 2) * BN * D_DIM;
            const __half* Vj = Vg + (size_t)(jj + 2) * BN * D_DIM;
            const int nx = (stage ^ 1) * 128;
            #pragma unroll
            for (int it = 0; it < 8; it++) {
                int idx = tid + it * 256;
                int r = idx >> 4;
                int c = (idx & 15) * 8;
                cpa16(sptr(&KS[nx + r][c]), Kj + (size_t)r * D_DIM + c);
                cpa16(sptr(&VS[nx + r][c]), Vj + (size_t)r * D_DIM + c);
            }
            asm volatile("cp.async.commit_group;");
            asm volatile("cp.async.wait_group 1;");
        } else {
            asm volatile("cp.async.wait_group 0;");
        }
        __syncthreads();

        for (int j2 = 0; j2 < 2; j2++) {
            const int j = jj + j2;
            const int kb = stage * 128 + j2 * BN;
            const bool fullSkip = (j * BN > q0 + m0 + 15);
            if (fullSkip) continue;

            // ---- S = Q @ K^T ----
            float sacc[8][4];
            #pragma unroll
            for (int n8 = 0; n8 < 8; n8++)
                #pragma unroll
                for (int e = 0; e < 4; e++) sacc[n8][e] = 0.f;

            #pragma unroll
            for (int n8 = 0; n8 < 8; n8++) {
                uint32_t kbf[8][2];
                #pragma unroll
                for (int qq = 0; qq < 4; qq++) {
                    unsigned a = sptr(&KS[kb + (n8 << 3) + l8][qq * 32 + (g << 3)]);
                    ldsm4(kbf[2 * qq][0], kbf[2 * qq][1], kbf[2 * qq + 1][0], kbf[2 * qq + 1][1], a);
                }
                #pragma unroll
                for (int kt = 0; kt < 8; kt++) mma16816(sacc[n8], qf[kt], kbf[kt]);
            }

            // ---- causal mask (only near-diagonal warp tiles) ----
            if (j * BN + BN - 1 > q0 + m0) {
                const int col0 = j * BN + ((lane & 3) << 1);
                #pragma unroll
                for (int n8 = 0; n8 < 8; n8++)
                    #pragma unroll
                    for (int e = 0; e < 4; e++) {
                        int col = col0 + (n8 << 3) + (e & 1);
                        int row = (e & 2) ? row1g : row0g;
                        if (col > row) sacc[n8][e] = NEG_INF;
                    }
            }

            // ---- fixed-bound softmax: no max, no rescale ----
            float ps0 = 0.f, ps1 = 0.f;
            uint32_t pf[4][4];
            #pragma unroll
            for (int n8 = 0; n8 < 8; n8++) {
                float p0 = ex2(fmaf(sacc[n8][0], c1, cadd0));
                float p1 = ex2(fmaf(sacc[n8][1], c1, cadd0));
                float p2 = ex2(fmaf(sacc[n8][2], c1, cadd1));
                float p3 = ex2(fmaf(sacc[n8][3], c1, cadd1));
                ps0 += p0 + p1;
                ps1 += p2 + p3;
                __half2 h01 = __floats2half2_rn(p0, p1);
                __half2 h23 = __floats2half2_rn(p2, p3);
                int kt = n8 >> 1;
                if (n8 & 1) {
                    pf[kt][2] = *reinterpret_cast<uint32_t*>(&h01);
                    pf[kt][3] = *reinterpret_cast<uint32_t*>(&h23);
                } else {
                    pf[kt][0] = *reinterpret_cast<uint32_t*>(&h01);
                    pf[kt][1] = *reinterpret_cast<uint32_t*>(&h23);
                }
            }
            lrow0 += ps0;
            lrow1 += ps1;

            // ---- O += P @ V ----
            #pragma unroll
            for (int kt = 0; kt < 4; kt++) {
                int k0 = kt << 4;
                #pragma unroll
                for (int e = 0; e < 8; e++) {
                    uint32_t r0, r1, r2, r3;
                    unsigned a = sptr(&VS[kb + k0 + ((g & 1) << 3) + l8][(e << 4) + ((g & 2) << 2)]);
                    ldsm4t(r0, r1, r2, r3, a);
                    uint32_t vb0[2] = {r0, r1}, vb1[2] = {r2, r3};
                    mma16816(oacc[2 * e], pf[kt], vb0);
                    mma16816(oacc[2 * e + 1], pf[kt], vb1);
                }
            }
        }
        __syncthreads();
    }

    // ---- epilogue ----
    lrow0 += __shfl_xor_sync(0xffffffffu, lrow0, 1);
    lrow0 += __shfl_xor_sync(0xffffffffu, lrow0, 2);
    lrow1 += __shfl_xor_sync(0xffffffffu, lrow1, 1);
    lrow1 += __shfl_xor_sync(0xffffffffu, lrow1, 2);
    float i0 = av / lrow0;
    float i1 = av / lrow1;
    size_t base0 = ((size_t)(b * S + row0g) * H_DIM + h) * D_DIM;
    size_t base1 = base0 + (size_t)8 * H_DIM * D_DIM;
    #pragma unroll
    for (int n = 0; n < 16; n++) {
        int col = (n << 3) + ((lane & 3) << 1);
        float2 v0 = {oacc[n][0] * i0, oacc[n][1] * i0};
        float2 v1 = {oacc[n][2] * i1, oacc[n][3] * i1};
        *(float2*)(out + base0 + col) = v0;
        *(float2*)(out + base1 + col) = v1;
    }
}

extern "C" void kernel_launch(void* const* d_in, const int* in_sizes, int n_in,
                              void* d_out, int out_size) {
    const float* q = (const float*)d_in[0];
    const float* k = (const float*)d_in[1];
    const float* v = (const float*)d_in[2];
    int n = in_sizes[0];
    int B = in_sizes[3] - 1;
    int total = n / (H_DIM * D_DIM);
    int S = total / B;
    int rows = total * H_DIM;

    cudaFuncSetAttribute(fa_kernel, cudaFuncAttributeMaxDynamicSharedMemorySize, SMEMSZ);

    absmax_kernel<<<dim3(296, 3), 256>>>(q, k, v, n);
    int n4 = n >> 2;
    quant_kernel<<<dim3((n4 + 255) / 256, 2), 256>>>(k, v, total, S);
    kmax_kernel<<<rows / 16, 256>>>(S);
    fa_kernel<<<dim3(S / BM, B * H_DIM), 256, SMEMSZ>>>((float*)d_out, q, S);
}